// round 8
// baseline (speedup 1.0000x reference)
#include <cuda_runtime.h>
#include <cuda_bf16.h>
#include <cstdint>

#define S_DIM 1024
#define B_DIM 32
#define D_DIM 1024
#define E_DIM 1024
#define M_TOTAL (S_DIM*B_DIM)
#define GRIDP 296     // 2 CTAs per SM (148 SMs)
#define NTASKS 1024   // 256 m-tiles x 4 E-quarters

// ---------------- device scratch ----------------
__device__ __nv_bfloat16 g_wv_bf[E_DIM*D_DIM];
__device__ __nv_bfloat16 g_val_bf[(size_t)M_TOTAL*D_DIM];
__device__ float g_pq[B_DIM*E_DIM];
__device__ float g_pq_part[8*B_DIM*E_DIM];
__device__ float g_scale_v[E_DIM];
__device__ float g_scores_part4[4*M_TOTAL];   // per E-quarter partial scores

__device__ __forceinline__ float fast_tanh(float x){
    float y; asm("tanh.approx.f32 %0, %1;" : "=f"(y) : "f"(x)); return y;
}
__device__ __forceinline__ uint32_t smem_u32(const void* p){
    return (uint32_t)__cvta_generic_to_shared(p);
}
__device__ __forceinline__ void cp_async16(uint32_t dst, const void* src){
    asm volatile("cp.async.cg.shared.global [%0], [%1], 16;\n" :: "r"(dst), "l"(src));
}
__device__ __forceinline__ void ldsm_x4(uint32_t* r, uint32_t addr){
    asm volatile("ldmatrix.sync.aligned.m8n8.x4.shared.b16 {%0,%1,%2,%3}, [%4];"
                 : "=r"(r[0]), "=r"(r[1]), "=r"(r[2]), "=r"(r[3]) : "r"(addr));
}

// ---------------- kernel 1: scale_v ----------------
__global__ void scale_v_kernel(const float* __restrict__ v, const float* __restrict__ g){
    __shared__ float red[32];
    int t = threadIdx.x;
    float x = v[t];
    float s = x*x;
    #pragma unroll
    for (int o=16;o;o>>=1) s += __shfl_xor_sync(0xffffffffu, s, o);
    if ((t&31)==0) red[t>>5] = s;
    __syncthreads();
    if (t < 32){
        float z = red[t];
        #pragma unroll
        for (int o=16;o;o>>=1) z += __shfl_xor_sync(0xffffffffu, z, o);
        if (t==0) red[0] = z;
    }
    __syncthreads();
    float scale = g[0] / sqrtf(red[0]);
    g_scale_v[t] = scale * x;
}

// ---------------- kernel 2: Wv fp32 -> bf16 ----------------
__global__ void wv_convert_kernel(const float* __restrict__ Wv){
    int i = blockIdx.x*256 + threadIdx.x;
    float4 f = reinterpret_cast<const float4*>(Wv)[i];
    __nv_bfloat162* dst = reinterpret_cast<__nv_bfloat162*>(g_wv_bf) + 2*(size_t)i;
    dst[0] = __floats2bfloat162_rn(f.x, f.y);
    dst[1] = __floats2bfloat162_rn(f.z, f.w);
}

// ---------------- kernel 2b: value fp32 -> bf16 ----------------
__global__ void val_convert_kernel(const float* __restrict__ value){
    size_t i = (size_t)blockIdx.x*256 + threadIdx.x;
    const float4* src = reinterpret_cast<const float4*>(value) + 2*i;
    float4 f0 = src[0], f1 = src[1];
    __nv_bfloat162 h0 = __floats2bfloat162_rn(f0.x, f0.y);
    __nv_bfloat162 h1 = __floats2bfloat162_rn(f0.z, f0.w);
    __nv_bfloat162 h2 = __floats2bfloat162_rn(f1.x, f1.y);
    __nv_bfloat162 h3 = __floats2bfloat162_rn(f1.z, f1.w);
    uint4 u;
    u.x = *(uint32_t*)&h0; u.y = *(uint32_t*)&h1;
    u.z = *(uint32_t*)&h2; u.w = *(uint32_t*)&h3;
    reinterpret_cast<uint4*>(g_val_bf)[i] = u;
}

// ---------------- kernel 3: pq split-k, float4 inner loop ----------------
__global__ void __launch_bounds__(256) pq_part_kernel(const float* __restrict__ query,
                                                      const float* __restrict__ Wq){
    __shared__ float4 sQ4[32*33];
    __shared__ float4 sW4[8*33];
    const int tid = threadIdx.x;
    const int eb = blockIdx.x, kb = blockIdx.y;
    const float4* query4 = reinterpret_cast<const float4*>(query);
    const float4* Wq4 = reinterpret_cast<const float4*>(Wq);
    #pragma unroll
    for (int t = 0; t < 4; t++){
        int idx = tid + t*256;
        int b = idx >> 5, k4 = idx & 31;
        sQ4[b*33 + k4] = query4[b*256 + kb*32 + k4];
    }
    {
        int e = tid >> 5, k4 = tid & 31;
        sW4[e*33 + k4] = Wq4[(size_t)(eb*8+e)*256 + kb*32 + k4];
    }
    __syncthreads();
    const int b = tid & 31, e = tid >> 5;
    float a0 = 0.f, a1 = 0.f;
    #pragma unroll
    for (int k4 = 0; k4 < 32; k4 += 2){
        float4 w0 = sW4[e*33 + k4],   q0 = sQ4[b*33 + k4];
        float4 w1 = sW4[e*33 + k4+1], q1 = sQ4[b*33 + k4+1];
        a0 += w0.x*q0.x + w0.y*q0.y + w0.z*q0.z + w0.w*q0.w;
        a1 += w1.x*q1.x + w1.y*q1.y + w1.z*q1.z + w1.w*q1.w;
    }
    g_pq_part[((size_t)kb*32 + b)*1024 + eb*8 + e] = a0 + a1;
}

__global__ void pq_reduce_kernel(const float* __restrict__ bq){
    int idx = blockIdx.x*256 + threadIdx.x;
    int e = idx & 1023;
    float s = bq[e];
    #pragma unroll
    for (int kb = 0; kb < 8; kb++) s += g_pq_part[(size_t)kb*32768 + idx];
    g_pq[idx] = s;
}

// ---------------- kernel 4: persistent score kernel, 2 CTAs/SM ----------------
// 296 CTAs (2/SM); tasks = (mt 0..255 [BM=128], ncg 0..3 [E-quarter=256]);
// stride-296 so SM pairs (bid, bid+148) carry 7 or 6 tasks (98.9% balance).
// Per task: 2 nc sub-chunks of 128, K in 16 chunks of 64. 3-stage cp.async ring.
#define KSTAGES 3
#define STAGE_BYTES 32768              // A 16K + B 16K
#define OFF_RED (KSTAGES*STAGE_BYTES)  // 98304
#define SMEM_TOTAL (OFF_RED + 2*128*4) // 99328 (x2 CTAs = 198656 <= 228KB)

__device__ __forceinline__ void score_load_chunk(uint32_t sb, int bid, int cr, int cc,
                                                 int stage, int c){
    const int ti = c >> 5, sub = c & 31;
    const int task = bid + ti*GRIDP;
    const int mt = task >> 2, ncg = task & 3;
    const int ncl = sub >> 4, kc = sub & 15;
    const __nv_bfloat16* Abase = g_val_bf + (size_t)(mt*128)*D_DIM + kc*64;
    const __nv_bfloat16* Bbase = g_wv_bf + (size_t)(ncg*256 + ncl*128)*D_DIM + kc*64;
    uint32_t dA = sb + stage*STAGE_BYTES;
    uint32_t dB = dA + 16384;
    #pragma unroll
    for (int t = 0; t < 4; t++){
        int r = cr + t*32;
        uint32_t off = (uint32_t)(r*128 + cc*16); off ^= (off>>3)&0x70;
        cp_async16(dA + off, Abase + (size_t)r*D_DIM + cc*8);
        cp_async16(dB + off, Bbase + (size_t)r*D_DIM + cc*8);
    }
    asm volatile("cp.async.commit_group;\n");
}

__global__ void __launch_bounds__(256,2) score_mma_kernel(){
    extern __shared__ char smem[];
    const uint32_t sb = smem_u32(smem);
    const int tid = threadIdx.x, lane = tid & 31, warp = tid >> 5;
    const int bid = blockIdx.x;
    const int wm = (warp & 3) * 32;      // M slice
    const int wn = (warp >> 2) * 64;     // N half
    const int g  = lane >> 2, t2 = (lane & 3) * 2;
    float* sRed = (float*)(smem + OFF_RED);

    const int nt = (NTASKS - 1 - bid) / GRIDP + 1;   // tasks for this CTA
    const int total = nt * 32;

    // ldmatrix per-lane geometry (SW128, 128B rows)
    const uint32_t lrow = ((lane >> 3) & 1) * 8 + (lane & 7);
    const uint32_t hi = lane >> 4;
    const uint32_t xsw = lrow & 7;
    uint32_t arow[2], brow[4];
    #pragma unroll
    for (int m2 = 0; m2 < 2; m2++) arow[m2] = (wm + m2*16 + lrow)*128;
    #pragma unroll
    for (int nb = 0; nb < 4; nb++) brow[nb] = (wn + nb*16 + lrow)*128;
    uint32_t csw[4];
    #pragma unroll
    for (int ks = 0; ks < 4; ks++) csw[ks] = (((uint32_t)(ks*2) + hi) ^ xsw) << 4;

    const int cr = tid >> 3, cc = tid & 7;

    score_load_chunk(sb, bid, cr, cc, 0, 0);
    score_load_chunk(sb, bid, cr, cc, 1, 1);

    int cur = 0;
    for (int ti = 0; ti < nt; ti++){
        const int task = bid + ti*GRIDP;
        const int mt = task >> 2, ncg = task & 3;
        float rs[2][2] = {{0.f,0.f},{0.f,0.f}};

        for (int ncl = 0; ncl < 2; ncl++){
            float acc[2][8][4];
            #pragma unroll
            for (int i=0;i<2;i++)
                #pragma unroll
                for (int j=0;j<8;j++)
                    #pragma unroll
                    for (int k=0;k<4;k++) acc[i][j][k]=0.f;

            #pragma unroll 1
            for (int kc = 0; kc < 16; kc++){
                const int c = ti*32 + ncl*16 + kc;
                if (c == total-1) asm volatile("cp.async.wait_group 0;\n");
                else              asm volatile("cp.async.wait_group 1;\n");
                __syncthreads();
                if (c + 2 < total){
                    int pf = cur + 2; if (pf >= 3) pf -= 3;
                    score_load_chunk(sb, bid, cr, cc, pf, c + 2);
                }
                const uint32_t stA = sb + cur*STAGE_BYTES;
                const uint32_t stB = stA + 16384;
                #pragma unroll
                for (int ks = 0; ks < 4; ks++){
                    uint32_t a[2][4], bq[4][4];
                    ldsm_x4(a[0], stA + arow[0] + csw[ks]);
                    ldsm_x4(a[1], stA + arow[1] + csw[ks]);
                    #pragma unroll
                    for (int nb = 0; nb < 4; nb++)
                        ldsm_x4(bq[nb], stB + brow[nb] + csw[ks]);
                    #pragma unroll
                    for (int m2 = 0; m2 < 2; m2++){
                        #pragma unroll
                        for (int nb = 0; nb < 4; nb++){
                            asm volatile(
                                "mma.sync.aligned.m16n8k16.row.col.f32.bf16.bf16.f32 "
                                "{%0,%1,%2,%3}, {%4,%5,%6,%7}, {%8,%9}, {%0,%1,%2,%3};\n"
                                : "+f"(acc[m2][2*nb][0]), "+f"(acc[m2][2*nb][1]),
                                  "+f"(acc[m2][2*nb][2]), "+f"(acc[m2][2*nb][3])
                                : "r"(a[m2][0]), "r"(a[m2][1]), "r"(a[m2][2]), "r"(a[m2][3]),
                                  "r"(bq[nb][0]), "r"(bq[nb][2]));
                            asm volatile(
                                "mma.sync.aligned.m16n8k16.row.col.f32.bf16.bf16.f32 "
                                "{%0,%1,%2,%3}, {%4,%5,%6,%7}, {%8,%9}, {%0,%1,%2,%3};\n"
                                : "+f"(acc[m2][2*nb+1][0]), "+f"(acc[m2][2*nb+1][1]),
                                  "+f"(acc[m2][2*nb+1][2]), "+f"(acc[m2][2*nb+1][3])
                                : "r"(a[m2][0]), "r"(a[m2][1]), "r"(a[m2][2]), "r"(a[m2][3]),
                                  "r"(bq[nb][1]), "r"(bq[nb][3]));
                        }
                    }
                }
                cur++; if (cur == 3) cur = 0;
            }

            // epilogue for this 128-col chunk (pq/sv from L2; no staged-smem access)
            const int e0 = ncg*256 + ncl*128;
            const float* svbase = g_scale_v + e0;
            float sv[16];
            #pragma unroll
            for (int nn = 0; nn < 8; nn++){
                sv[2*nn  ] = svbase[wn + nn*8 + t2];
                sv[2*nn+1] = svbase[wn + nn*8 + t2 + 1];
            }
            #pragma unroll
            for (int m2 = 0; m2 < 2; m2++){
                #pragma unroll
                for (int o = 0; o < 2; o++){
                    int b = (wm + m2*16 + g + o*8) & 31;
                    const float* prow = g_pq + (size_t)b*E_DIM + e0;
                    float acc_s = 0.f;
                    #pragma unroll
                    for (int nn = 0; nn < 8; nn++){
                        int cidx = wn + nn*8 + t2;
                        acc_s += fast_tanh(acc[m2][nn][2*o  ] + prow[cidx  ]) * sv[2*nn  ]
                               + fast_tanh(acc[m2][nn][2*o+1] + prow[cidx+1]) * sv[2*nn+1];
                    }
                    rs[m2][o] += acc_s;
                }
            }
        }

        // write this task's partial scores
        #pragma unroll
        for (int m2 = 0; m2 < 2; m2++)
            #pragma unroll
            for (int o = 0; o < 2; o++){
                rs[m2][o] += __shfl_xor_sync(0xffffffffu, rs[m2][o], 1);
                rs[m2][o] += __shfl_xor_sync(0xffffffffu, rs[m2][o], 2);
            }
        __syncthreads();
        if ((lane & 3) == 0){
            #pragma unroll
            for (int m2 = 0; m2 < 2; m2++)
                #pragma unroll
                for (int o = 0; o < 2; o++)
                    sRed[(warp>>2)*128 + wm + m2*16 + o*8 + g] = rs[m2][o];
        }
        __syncthreads();
        if (tid < 128)
            g_scores_part4[(size_t)ncg*M_TOTAL + mt*128 + tid] = sRed[tid] + sRed[128 + tid];
    }
}

// ---------------- kernel 5: fused partial-sum + softmax + context ----------------
__global__ void __launch_bounds__(256) softmax_ctx_kernel(
        const unsigned char* __restrict__ mask, const float* __restrict__ value,
        float* __restrict__ ctx, float* __restrict__ out1, float* __restrict__ out2){
    __shared__ float sa[1024];
    __shared__ float red[8];
    const int tid = threadIdx.x, lane = tid & 31, warp = tid >> 5;
    const int b = blockIdx.y, dsl = blockIdx.x;

    float x[4];
    #pragma unroll
    for (int j = 0; j < 4; j++){
        int s = tid + j*256;
        int idx = s*B_DIM + b;
        float v = g_scores_part4[idx] + g_scores_part4[M_TOTAL + idx]
                + g_scores_part4[2*M_TOTAL + idx] + g_scores_part4[3*M_TOTAL + idx];
        if (mask[idx]) v = -1e30f;
        x[j] = v;
    }
    float m = fmaxf(fmaxf(x[0], x[1]), fmaxf(x[2], x[3]));
    #pragma unroll
    for (int o=16;o;o>>=1) m = fmaxf(m, __shfl_xor_sync(0xffffffffu, m, o));
    if (lane == 0) red[warp] = m;
    __syncthreads();
    float bm = red[0];
    #pragma unroll
    for (int w = 1; w < 8; w++) bm = fmaxf(bm, red[w]);

    float e[4], t = 0.f;
    #pragma unroll
    for (int j = 0; j < 4; j++){ e[j] = __expf(x[j] - bm); t += e[j]; }
    #pragma unroll
    for (int o=16;o;o>>=1) t += __shfl_xor_sync(0xffffffffu, t, o);
    __syncthreads();
    if (lane == 0) red[warp] = t;
    __syncthreads();
    float bs = ((red[0]+red[1])+(red[2]+red[3])) + ((red[4]+red[5])+(red[6]+red[7]));
    float inv = 1.f / bs;

    #pragma unroll
    for (int j = 0; j < 4; j++){
        int s = tid + j*256;
        float a = e[j] * inv;
        sa[s] = a;
        if (dsl == 0){
            int idx = s*B_DIM + b;
            if (out1) out1[idx] = a;
            if (out2) out2[idx] = a;
        }
    }
    __syncthreads();

    const int d = dsl*256 + tid;
    const float* vp = value + (size_t)b*D_DIM + d;
    float acc = 0.f;
    #pragma unroll 1
    for (int s = 0; s < S_DIM; s += 8){
        float a[8], vv[8];
        #pragma unroll
        for (int i = 0; i < 8; i++){
            a[i]  = sa[s+i];
            vv[i] = vp[(size_t)(s+i)*B_DIM*D_DIM];
        }
        #pragma unroll
        for (int i = 0; i < 8; i++) acc += a[i]*vv[i];
    }
    ctx[(size_t)b*D_DIM + d] = acc;
}

// ---------------- launch ----------------
extern "C" void kernel_launch(void* const* d_in, const int* in_sizes, int n_in,
                              void* d_out, int out_size){
    const float* query = (const float*)d_in[0];
    const float* value = (const float*)d_in[1];
    const unsigned char* mask = (const unsigned char*)d_in[2];
    const float* Wq = (const float*)d_in[3];
    const float* bq = (const float*)d_in[4];
    const float* Wv = (const float*)d_in[5];
    const float* v  = (const float*)d_in[6];
    const float* g  = (const float*)d_in[7];
    float* out = (float*)d_out;
    (void)in_sizes; (void)n_in;

    cudaFuncSetAttribute(score_mma_kernel, cudaFuncAttributeMaxDynamicSharedMemorySize, SMEM_TOTAL);

    scale_v_kernel<<<1, 1024>>>(v, g);
    wv_convert_kernel<<<1024, 256>>>(Wv);
    val_convert_kernel<<<16384, 256>>>(value);
    pq_part_kernel<<<dim3(128,8), 256>>>(query, Wq);
    pq_reduce_kernel<<<128, 256>>>(bq);
    score_mma_kernel<<<GRIDP, 256, SMEM_TOTAL>>>();

    float* attn1 = (out_size >= 65536) ? out + 32768 : nullptr;
    float* attn2 = (out_size >= 98304) ? out + 65536 : nullptr;
    softmax_ctx_kernel<<<dim3(4,32), 256>>>(mask, value, out, attn1, attn2);
}

// round 9
// speedup vs baseline: 1.0089x; 1.0089x over previous
#include <cuda_runtime.h>
#include <cuda_bf16.h>
#include <cstdint>

#define S_DIM 1024
#define B_DIM 32
#define D_DIM 1024
#define E_DIM 1024
#define M_TOTAL (S_DIM*B_DIM)

// ---------------- device scratch ----------------
__device__ __nv_bfloat16 g_wv_bf[E_DIM*D_DIM];
__device__ __nv_bfloat16 g_val_bf[(size_t)M_TOTAL*D_DIM];
__device__ float g_pq[B_DIM*E_DIM];
__device__ float g_pq_part[8*B_DIM*E_DIM];
__device__ float g_scale_v[E_DIM];
__device__ float g_scores_part4[4*M_TOTAL];   // per E-quarter partial scores

__device__ __forceinline__ float fast_tanh(float x){
    float y; asm("tanh.approx.f32 %0, %1;" : "=f"(y) : "f"(x)); return y;
}
__device__ __forceinline__ uint32_t smem_u32(const void* p){
    return (uint32_t)__cvta_generic_to_shared(p);
}
__device__ __forceinline__ void cp_async16(uint32_t dst, const void* src){
    asm volatile("cp.async.cg.shared.global [%0], [%1], 16;\n" :: "r"(dst), "l"(src));
}
__device__ __forceinline__ void ldsm_x4(uint32_t* r, uint32_t addr){
    asm volatile("ldmatrix.sync.aligned.m8n8.x4.shared.b16 {%0,%1,%2,%3}, [%4];"
                 : "=r"(r[0]), "=r"(r[1]), "=r"(r[2]), "=r"(r[3]) : "r"(addr));
}

// ---------------- kernel 1 (launch 1): fused prep ----------------
// blocks [0,16384): value fp32->bf16 ; [16384,17408): Wv fp32->bf16 ; 17408: scale_v
__global__ void __launch_bounds__(256) prep_kernel(const float* __restrict__ value,
        const float* __restrict__ Wv, const float* __restrict__ v,
        const float* __restrict__ g){
    const int bid = blockIdx.x, tid = threadIdx.x;
    if (bid < 16384){
        size_t i = (size_t)bid*256 + tid;
        const float4* src = reinterpret_cast<const float4*>(value) + 2*i;
        float4 f0 = src[0], f1 = src[1];
        __nv_bfloat162 h0 = __floats2bfloat162_rn(f0.x, f0.y);
        __nv_bfloat162 h1 = __floats2bfloat162_rn(f0.z, f0.w);
        __nv_bfloat162 h2 = __floats2bfloat162_rn(f1.x, f1.y);
        __nv_bfloat162 h3 = __floats2bfloat162_rn(f1.z, f1.w);
        uint4 u;
        u.x = *(uint32_t*)&h0; u.y = *(uint32_t*)&h1;
        u.z = *(uint32_t*)&h2; u.w = *(uint32_t*)&h3;
        reinterpret_cast<uint4*>(g_val_bf)[i] = u;
    } else if (bid < 17408){
        int i = (bid - 16384)*256 + tid;
        float4 f = reinterpret_cast<const float4*>(Wv)[i];
        __nv_bfloat162* dst = reinterpret_cast<__nv_bfloat162*>(g_wv_bf) + 2*(size_t)i;
        dst[0] = __floats2bfloat162_rn(f.x, f.y);
        dst[1] = __floats2bfloat162_rn(f.z, f.w);
    } else {
        __shared__ float red[8];
        float4 xv = reinterpret_cast<const float4*>(v)[tid];
        float s = xv.x*xv.x + xv.y*xv.y + xv.z*xv.z + xv.w*xv.w;
        #pragma unroll
        for (int o=16;o;o>>=1) s += __shfl_xor_sync(0xffffffffu, s, o);
        if ((tid&31)==0) red[tid>>5] = s;
        __syncthreads();
        float tot = ((red[0]+red[1])+(red[2]+red[3])) + ((red[4]+red[5])+(red[6]+red[7]));
        float scale = g[0] / sqrtf(tot);
        float4 o4 = {scale*xv.x, scale*xv.y, scale*xv.z, scale*xv.w};
        reinterpret_cast<float4*>(g_scale_v)[tid] = o4;
    }
}

// ---------------- kernel 2 (launch 2): pq split-k ----------------
__global__ void __launch_bounds__(256) pq_part_kernel(const float* __restrict__ query,
                                                      const float* __restrict__ Wq){
    __shared__ float4 sQ4[32*33];
    __shared__ float4 sW4[8*33];
    const int tid = threadIdx.x;
    const int eb = blockIdx.x, kb = blockIdx.y;
    const float4* query4 = reinterpret_cast<const float4*>(query);
    const float4* Wq4 = reinterpret_cast<const float4*>(Wq);
    #pragma unroll
    for (int t = 0; t < 4; t++){
        int idx = tid + t*256;
        int b = idx >> 5, k4 = idx & 31;
        sQ4[b*33 + k4] = query4[b*256 + kb*32 + k4];
    }
    {
        int e = tid >> 5, k4 = tid & 31;
        sW4[e*33 + k4] = Wq4[(size_t)(eb*8+e)*256 + kb*32 + k4];
    }
    __syncthreads();
    const int b = tid & 31, e = tid >> 5;
    float a0 = 0.f, a1 = 0.f;
    #pragma unroll
    for (int k4 = 0; k4 < 32; k4 += 2){
        float4 w0 = sW4[e*33 + k4],   q0 = sQ4[b*33 + k4];
        float4 w1 = sW4[e*33 + k4+1], q1 = sQ4[b*33 + k4+1];
        a0 += w0.x*q0.x + w0.y*q0.y + w0.z*q0.z + w0.w*q0.w;
        a1 += w1.x*q1.x + w1.y*q1.y + w1.z*q1.z + w1.w*q1.w;
    }
    g_pq_part[((size_t)kb*32 + b)*1024 + eb*8 + e] = a0 + a1;
}

// ---------------- kernel 3 (launch 3): pq reduce ----------------
__global__ void pq_reduce_kernel(const float* __restrict__ bq){
    int idx = blockIdx.x*256 + threadIdx.x;
    int e = idx & 1023;
    float s = bq[e];
    #pragma unroll
    for (int kb = 0; kb < 8; kb++) s += g_pq_part[(size_t)kb*32768 + idx];
    g_pq[idx] = s;
}

// ---------------- kernel 4 (launch 4 -> PROFILED): score kernel (R4 config) ----
// grid 256, BM=128, 2 CTAs/SM. E in 8 chunks of 128 (nc), K in 64-wide chunks
// (gk 0..127), 3-stage cp.async ring, SW128 swizzle, warp tile 32x64.
#define KSTAGES 3
#define STAGE_BYTES 32768              // A 16K + B 16K
#define OFF_RED (KSTAGES*STAGE_BYTES)  // 98304
#define SMEM_TOTAL (OFF_RED + 2*128*4) // 99328

__device__ __forceinline__ void score_load_stage(uint32_t sb, int m0, int cr, int cc,
                                                 int stage, int gk){
    const int i = gk & 15, nc = gk >> 4;
    const __nv_bfloat16* Abase = g_val_bf + (size_t)m0*D_DIM + i*64;
    const __nv_bfloat16* Bbase = g_wv_bf + (size_t)(nc*128)*D_DIM + i*64;
    uint32_t dA = sb + stage*STAGE_BYTES, dB = dA + 16384;
    #pragma unroll
    for (int t = 0; t < 4; t++){
        int r = cr + t*32;
        uint32_t off = (uint32_t)(r*128 + cc*16);
        off ^= (off>>3)&0x70;
        cp_async16(dA + off, Abase + (size_t)r*D_DIM + cc*8);
        cp_async16(dB + off, Bbase + (size_t)r*D_DIM + cc*8);
    }
    asm volatile("cp.async.commit_group;\n");
}

__global__ void __launch_bounds__(256,2) score_mma_kernel(){
    extern __shared__ char smem[];
    const uint32_t sb = smem_u32(smem);
    const int tid = threadIdx.x, lane = tid & 31, warp = tid >> 5;
    const int m0 = blockIdx.x * 128;
    const int wm = (warp & 3) * 32;      // M slice
    const int wn = (warp >> 2) * 64;     // N half
    const int g  = lane >> 2, t2 = (lane & 3) * 2;
    float* sRed = (float*)(smem + OFF_RED);

    // ldmatrix per-lane geometry (SW128, 128B rows)
    const uint32_t lrow = ((lane >> 3) & 1) * 8 + (lane & 7);
    const uint32_t hi = lane >> 4;
    const uint32_t xsw = lrow & 7;
    uint32_t arow[2], brow[4];
    #pragma unroll
    for (int m2 = 0; m2 < 2; m2++) arow[m2] = (wm + m2*16 + lrow)*128;
    #pragma unroll
    for (int nb = 0; nb < 4; nb++) brow[nb] = (wn + nb*16 + lrow)*128;
    uint32_t csw[4];
    #pragma unroll
    for (int ks = 0; ks < 4; ks++) csw[ks] = (((uint32_t)(ks*2) + hi) ^ xsw) << 4;

    const int cr = tid >> 3, cc = tid & 7;

    score_load_stage(sb, m0, cr, cc, 0, 0);
    score_load_stage(sb, m0, cr, cc, 1, 1);

    int cur = 0;
    for (int nc = 0; nc < 8; nc++){
        float acc[2][8][4];
        #pragma unroll
        for (int i=0;i<2;i++)
            #pragma unroll
            for (int j=0;j<8;j++)
                #pragma unroll
                for (int k=0;k<4;k++) acc[i][j][k]=0.f;

        #pragma unroll 1
        for (int i = 0; i < 16; i++){
            const int gk = nc*16 + i;
            if (gk == 127) asm volatile("cp.async.wait_group 0;\n");
            else           asm volatile("cp.async.wait_group 1;\n");
            __syncthreads();
            if (gk + 2 < 128){
                int pf = cur + 2; if (pf >= 3) pf -= 3;
                score_load_stage(sb, m0, cr, cc, pf, gk + 2);
            }
            const uint32_t stA = sb + cur*STAGE_BYTES;
            const uint32_t stB = stA + 16384;
            #pragma unroll
            for (int ks = 0; ks < 4; ks++){
                uint32_t a[2][4], bq[4][4];
                ldsm_x4(a[0], stA + arow[0] + csw[ks]);
                ldsm_x4(a[1], stA + arow[1] + csw[ks]);
                #pragma unroll
                for (int nb = 0; nb < 4; nb++)
                    ldsm_x4(bq[nb], stB + brow[nb] + csw[ks]);
                #pragma unroll
                for (int m2 = 0; m2 < 2; m2++){
                    #pragma unroll
                    for (int nb = 0; nb < 4; nb++){
                        asm volatile(
                            "mma.sync.aligned.m16n8k16.row.col.f32.bf16.bf16.f32 "
                            "{%0,%1,%2,%3}, {%4,%5,%6,%7}, {%8,%9}, {%0,%1,%2,%3};\n"
                            : "+f"(acc[m2][2*nb][0]), "+f"(acc[m2][2*nb][1]),
                              "+f"(acc[m2][2*nb][2]), "+f"(acc[m2][2*nb][3])
                            : "r"(a[m2][0]), "r"(a[m2][1]), "r"(a[m2][2]), "r"(a[m2][3]),
                              "r"(bq[nb][0]), "r"(bq[nb][2]));
                        asm volatile(
                            "mma.sync.aligned.m16n8k16.row.col.f32.bf16.bf16.f32 "
                            "{%0,%1,%2,%3}, {%4,%5,%6,%7}, {%8,%9}, {%0,%1,%2,%3};\n"
                            : "+f"(acc[m2][2*nb+1][0]), "+f"(acc[m2][2*nb+1][1]),
                              "+f"(acc[m2][2*nb+1][2]), "+f"(acc[m2][2*nb+1][3])
                            : "r"(a[m2][0]), "r"(a[m2][1]), "r"(a[m2][2]), "r"(a[m2][3]),
                              "r"(bq[nb][1]), "r"(bq[nb][3]));
                    }
                }
            }
            cur++; if (cur == 3) cur = 0;
        }

        // epilogue: rs += tanh(acc + pq) * scale_v ; pq/sv from L2
        const float* svbase = g_scale_v + nc*128;
        float sv[16];
        #pragma unroll
        for (int nn = 0; nn < 8; nn++){
            sv[2*nn  ] = svbase[wn + nn*8 + t2];
            sv[2*nn+1] = svbase[wn + nn*8 + t2 + 1];
        }
        float rs[2][2] = {{0.f,0.f},{0.f,0.f}};
        #pragma unroll
        for (int m2 = 0; m2 < 2; m2++){
            #pragma unroll
            for (int o = 0; o < 2; o++){
                int b = (wm + m2*16 + g + o*8) & 31;
                const float* prow = g_pq + (size_t)b*E_DIM + nc*128;
                float acc_s = 0.f;
                #pragma unroll
                for (int nn = 0; nn < 8; nn++){
                    int c = wn + nn*8 + t2;
                    acc_s += fast_tanh(acc[m2][nn][2*o  ] + prow[c  ]) * sv[2*nn  ]
                           + fast_tanh(acc[m2][nn][2*o+1] + prow[c+1]) * sv[2*nn+1];
                }
                rs[m2][o] = acc_s;
            }
        }
        // quad reduce + cross-N-warp reduce, write this nc's partial scores
        #pragma unroll
        for (int m2 = 0; m2 < 2; m2++)
            #pragma unroll
            for (int o = 0; o < 2; o++){
                rs[m2][o] += __shfl_xor_sync(0xffffffffu, rs[m2][o], 1);
                rs[m2][o] += __shfl_xor_sync(0xffffffffu, rs[m2][o], 2);
            }
        __syncthreads();
        if ((lane & 3) == 0){
            #pragma unroll
            for (int m2 = 0; m2 < 2; m2++)
                #pragma unroll
                for (int o = 0; o < 2; o++)
                    sRed[(warp>>2)*128 + wm + m2*16 + o*8 + g] = rs[m2][o];
        }
        __syncthreads();
        if (tid < 128){
            float val = sRed[tid] + sRed[128 + tid];
            int ncg = nc >> 1;
            if (nc & 1){
                g_scores_part4[(size_t)ncg*M_TOTAL + m0 + tid] += val;
            } else {
                g_scores_part4[(size_t)ncg*M_TOTAL + m0 + tid] = val;
            }
        }
    }
}

// ---------------- kernel 5 (launch 5): fused partial-sum + softmax + context ----
__global__ void __launch_bounds__(256) softmax_ctx_kernel(
        const unsigned char* __restrict__ mask, const float* __restrict__ value,
        float* __restrict__ ctx, float* __restrict__ out1, float* __restrict__ out2){
    __shared__ float sa[1024];
    __shared__ float red[8];
    const int tid = threadIdx.x, lane = tid & 31, warp = tid >> 5;
    const int b = blockIdx.y, dsl = blockIdx.x;

    float x[4];
    #pragma unroll
    for (int j = 0; j < 4; j++){
        int s = tid + j*256;
        int idx = s*B_DIM + b;
        float v = g_scores_part4[idx] + g_scores_part4[M_TOTAL + idx]
                + g_scores_part4[2*M_TOTAL + idx] + g_scores_part4[3*M_TOTAL + idx];
        if (mask[idx]) v = -1e30f;
        x[j] = v;
    }
    float m = fmaxf(fmaxf(x[0], x[1]), fmaxf(x[2], x[3]));
    #pragma unroll
    for (int o=16;o;o>>=1) m = fmaxf(m, __shfl_xor_sync(0xffffffffu, m, o));
    if (lane == 0) red[warp] = m;
    __syncthreads();
    float bm = red[0];
    #pragma unroll
    for (int w = 1; w < 8; w++) bm = fmaxf(bm, red[w]);

    float e[4], t = 0.f;
    #pragma unroll
    for (int j = 0; j < 4; j++){ e[j] = __expf(x[j] - bm); t += e[j]; }
    #pragma unroll
    for (int o=16;o;o>>=1) t += __shfl_xor_sync(0xffffffffu, t, o);
    __syncthreads();
    if (lane == 0) red[warp] = t;
    __syncthreads();
    float bs = ((red[0]+red[1])+(red[2]+red[3])) + ((red[4]+red[5])+(red[6]+red[7]));
    float inv = 1.f / bs;

    #pragma unroll
    for (int j = 0; j < 4; j++){
        int s = tid + j*256;
        float a = e[j] * inv;
        sa[s] = a;
        if (dsl == 0){
            int idx = s*B_DIM + b;
            if (out1) out1[idx] = a;
            if (out2) out2[idx] = a;
        }
    }
    __syncthreads();

    const int d = dsl*256 + tid;
    const float* vp = value + (size_t)b*D_DIM + d;
    float acc = 0.f;
    #pragma unroll 1
    for (int s = 0; s < S_DIM; s += 8){
        float a[8], vv[8];
        #pragma unroll
        for (int i = 0; i < 8; i++){
            a[i]  = sa[s+i];
            vv[i] = vp[(size_t)(s+i)*B_DIM*D_DIM];
        }
        #pragma unroll
        for (int i = 0; i < 8; i++) acc += a[i]*vv[i];
    }
    ctx[(size_t)b*D_DIM + d] = acc;
}

// ---------------- launch ----------------
extern "C" void kernel_launch(void* const* d_in, const int* in_sizes, int n_in,
                              void* d_out, int out_size){
    const float* query = (const float*)d_in[0];
    const float* value = (const float*)d_in[1];
    const unsigned char* mask = (const unsigned char*)d_in[2];
    const float* Wq = (const float*)d_in[3];
    const float* bq = (const float*)d_in[4];
    const float* Wv = (const float*)d_in[5];
    const float* v  = (const float*)d_in[6];
    const float* g  = (const float*)d_in[7];
    float* out = (float*)d_out;
    (void)in_sizes; (void)n_in;

    cudaFuncSetAttribute(score_mma_kernel, cudaFuncAttributeMaxDynamicSharedMemorySize, SMEM_TOTAL);

    prep_kernel<<<17409, 256>>>(value, Wv, v, g);          // launch 1
    pq_part_kernel<<<dim3(128,8), 256>>>(query, Wq);       // launch 2
    pq_reduce_kernel<<<128, 256>>>(bq);                    // launch 3
    score_mma_kernel<<<256, 256, SMEM_TOTAL>>>();          // launch 4 (profiled)

    float* attn1 = (out_size >= 65536) ? out + 32768 : nullptr;
    float* attn2 = (out_size >= 98304) ? out + 65536 : nullptr;
    softmax_ctx_kernel<<<dim3(4,32), 256>>>(mask, value, out, attn1, attn2);  // launch 5
}

// round 11
// speedup vs baseline: 1.0529x; 1.0436x over previous
#include <cuda_runtime.h>
#include <cuda_bf16.h>
#include <cstdint>

#define S_DIM 1024
#define B_DIM 32
#define D_DIM 1024
#define E_DIM 1024
#define M_TOTAL (S_DIM*B_DIM)

// ---------------- device scratch ----------------
__device__ __nv_bfloat16 g_wv_bf[E_DIM*D_DIM];
__device__ __nv_bfloat16 g_val_bf[(size_t)M_TOTAL*D_DIM];
__device__ float g_pq[B_DIM*E_DIM];
__device__ float g_pq_part[8*B_DIM*E_DIM];
__device__ float g_scale_v[E_DIM];
__device__ float g_scores[M_TOTAL];          // raw scores -> attn
__device__ float g_ctx_part[4*B_DIM*D_DIM];  // context s-split partials

__device__ __forceinline__ float fast_tanh(float x){
    float y; asm("tanh.approx.f32 %0, %1;" : "=f"(y) : "f"(x)); return y;
}
__device__ __forceinline__ uint32_t smem_u32(const void* p){
    return (uint32_t)__cvta_generic_to_shared(p);
}
__device__ __forceinline__ void cp_async16(uint32_t dst, const void* src){
    asm volatile("cp.async.cg.shared.global [%0], [%1], 16;\n" :: "r"(dst), "l"(src));
}
__device__ __forceinline__ void ldsm_x4(uint32_t* r, uint32_t addr){
    asm volatile("ldmatrix.sync.aligned.m8n8.x4.shared.b16 {%0,%1,%2,%3}, [%4];"
                 : "=r"(r[0]), "=r"(r[1]), "=r"(r[2]), "=r"(r[3]) : "r"(addr));
}

// ---------------- kernel 1 (launch 1): fused prep ----------------
__global__ void __launch_bounds__(256) prep_kernel(const float* __restrict__ value,
        const float* __restrict__ Wv, const float* __restrict__ v,
        const float* __restrict__ g){
    const int bid = blockIdx.x, tid = threadIdx.x;
    if (bid < 16384){
        size_t i = (size_t)bid*256 + tid;
        const float4* src = reinterpret_cast<const float4*>(value) + 2*i;
        float4 f0 = src[0], f1 = src[1];
        __nv_bfloat162 h0 = __floats2bfloat162_rn(f0.x, f0.y);
        __nv_bfloat162 h1 = __floats2bfloat162_rn(f0.z, f0.w);
        __nv_bfloat162 h2 = __floats2bfloat162_rn(f1.x, f1.y);
        __nv_bfloat162 h3 = __floats2bfloat162_rn(f1.z, f1.w);
        uint4 u;
        u.x = *(uint32_t*)&h0; u.y = *(uint32_t*)&h1;
        u.z = *(uint32_t*)&h2; u.w = *(uint32_t*)&h3;
        reinterpret_cast<uint4*>(g_val_bf)[i] = u;
    } else if (bid < 17408){
        int i = (bid - 16384)*256 + tid;
        float4 f = reinterpret_cast<const float4*>(Wv)[i];
        __nv_bfloat162* dst = reinterpret_cast<__nv_bfloat162*>(g_wv_bf) + 2*(size_t)i;
        dst[0] = __floats2bfloat162_rn(f.x, f.y);
        dst[1] = __floats2bfloat162_rn(f.z, f.w);
    } else {
        __shared__ float red[8];
        float4 xv = reinterpret_cast<const float4*>(v)[tid];
        float s = xv.x*xv.x + xv.y*xv.y + xv.z*xv.z + xv.w*xv.w;
        #pragma unroll
        for (int o=16;o;o>>=1) s += __shfl_xor_sync(0xffffffffu, s, o);
        if ((tid&31)==0) red[tid>>5] = s;
        __syncthreads();
        float tot = ((red[0]+red[1])+(red[2]+red[3])) + ((red[4]+red[5])+(red[6]+red[7]));
        float scale = g[0] / sqrtf(tot);
        float4 o4 = {scale*xv.x, scale*xv.y, scale*xv.z, scale*xv.w};
        reinterpret_cast<float4*>(g_scale_v)[tid] = o4;
    }
}

// ---------------- kernel 2 (launch 2): pq split-k ----------------
__global__ void __launch_bounds__(256) pq_part_kernel(const float* __restrict__ query,
                                                      const float* __restrict__ Wq){
    __shared__ float4 sQ4[32*33];
    __shared__ float4 sW4[8*33];
    const int tid = threadIdx.x;
    const int eb = blockIdx.x, kb = blockIdx.y;
    const float4* query4 = reinterpret_cast<const float4*>(query);
    const float4* Wq4 = reinterpret_cast<const float4*>(Wq);
    #pragma unroll
    for (int t = 0; t < 4; t++){
        int idx = tid + t*256;
        int b = idx >> 5, k4 = idx & 31;
        sQ4[b*33 + k4] = query4[b*256 + kb*32 + k4];
    }
    {
        int e = tid >> 5, k4 = tid & 31;
        sW4[e*33 + k4] = Wq4[(size_t)(eb*8+e)*256 + kb*32 + k4];
    }
    __syncthreads();
    const int b = tid & 31, e = tid >> 5;
    float a0 = 0.f, a1 = 0.f;
    #pragma unroll
    for (int k4 = 0; k4 < 32; k4 += 2){
        float4 w0 = sW4[e*33 + k4],   q0 = sQ4[b*33 + k4];
        float4 w1 = sW4[e*33 + k4+1], q1 = sQ4[b*33 + k4+1];
        a0 += w0.x*q0.x + w0.y*q0.y + w0.z*q0.z + w0.w*q0.w;
        a1 += w1.x*q1.x + w1.y*q1.y + w1.z*q1.z + w1.w*q1.w;
    }
    g_pq_part[((size_t)kb*32 + b)*1024 + eb*8 + e] = a0 + a1;
}

// ---------------- kernel 3 (launch 3): pq reduce ----------------
__global__ void pq_reduce_kernel(const float* __restrict__ bq){
    int idx = blockIdx.x*256 + threadIdx.x;
    int e = idx & 1023;
    float s = bq[e];
    #pragma unroll
    for (int kb = 0; kb < 8; kb++) s += g_pq_part[(size_t)kb*32768 + idx];
    g_pq[idx] = s;
}

// ---------------- kernel 4 (launch 4 -> PROFILED): score kernel ----------------
// grid 256, BM=128, 2 CTAs/SM, E in 8 chunks of 128, 3-stage cp.async ring,
// SW128 swizzle, warp tile 32x64. rs accumulated across all nc (one final write).
// ks-stagger: odd warps traverse ks in reverse to de-lockstep ldsm bursts.
#define KSTAGES 3
#define STAGE_BYTES 32768
#define OFF_RED (KSTAGES*STAGE_BYTES)
#define SMEM_TOTAL (OFF_RED + 2*128*4)

__device__ __forceinline__ void score_load_stage(uint32_t sb, int m0, int cr, int cc,
                                                 int stage, int gk){
    const int i = gk & 15, nc = gk >> 4;
    const __nv_bfloat16* Abase = g_val_bf + (size_t)m0*D_DIM + i*64;
    const __nv_bfloat16* Bbase = g_wv_bf + (size_t)(nc*128)*D_DIM + i*64;
    uint32_t dA = sb + stage*STAGE_BYTES, dB = dA + 16384;
    #pragma unroll
    for (int t = 0; t < 4; t++){
        int r = cr + t*32;
        uint32_t off = (uint32_t)(r*128 + cc*16);
        off ^= (off>>3)&0x70;
        cp_async16(dA + off, Abase + (size_t)r*D_DIM + cc*8);
        cp_async16(dB + off, Bbase + (size_t)r*D_DIM + cc*8);
    }
    asm volatile("cp.async.commit_group;\n");
}

__global__ void __launch_bounds__(256,2) score_mma_kernel(){
    extern __shared__ char smem[];
    const uint32_t sb = smem_u32(smem);
    const int tid = threadIdx.x, lane = tid & 31, warp = tid >> 5;
    const int m0 = blockIdx.x * 128;
    const int wm = (warp & 3) * 32;
    const int wn = (warp >> 2) * 64;
    const int g  = lane >> 2, t2 = (lane & 3) * 2;
    const int wrev = warp & 1;           // odd warps reverse ks order
    float* sRed = (float*)(smem + OFF_RED);

    const uint32_t lrow = ((lane >> 3) & 1) * 8 + (lane & 7);
    const uint32_t hi = lane >> 4;
    const uint32_t xsw = lrow & 7;
    uint32_t arow[2], brow[4];
    #pragma unroll
    for (int m2 = 0; m2 < 2; m2++) arow[m2] = (wm + m2*16 + lrow)*128;
    #pragma unroll
    for (int nb = 0; nb < 4; nb++) brow[nb] = (wn + nb*16 + lrow)*128;
    uint32_t csw[4];
    #pragma unroll
    for (int ks = 0; ks < 4; ks++) csw[ks] = (((uint32_t)(ks*2) + hi) ^ xsw) << 4;

    const int cr = tid >> 3, cc = tid & 7;

    float rs[2][2] = {{0.f,0.f},{0.f,0.f}};

    score_load_stage(sb, m0, cr, cc, 0, 0);
    score_load_stage(sb, m0, cr, cc, 1, 1);

    int cur = 0;
    for (int nc = 0; nc < 8; nc++){
        float acc[2][8][4];
        #pragma unroll
        for (int i=0;i<2;i++)
            #pragma unroll
            for (int j=0;j<8;j++)
                #pragma unroll
                for (int k=0;k<4;k++) acc[i][j][k]=0.f;

        #pragma unroll 1
        for (int i = 0; i < 16; i++){
            const int gk = nc*16 + i;
            if (gk == 127) asm volatile("cp.async.wait_group 0;\n");
            else           asm volatile("cp.async.wait_group 1;\n");
            __syncthreads();
            if (gk + 2 < 128){
                int pf = cur + 2; if (pf >= 3) pf -= 3;
                score_load_stage(sb, m0, cr, cc, pf, gk + 2);
            }
            const uint32_t stA = sb + cur*STAGE_BYTES;
            const uint32_t stB = stA + 16384;
            #pragma unroll
            for (int ks = 0; ks < 4; ks++){
                const int kse = wrev ? 3 - ks : ks;   // stagger crossbar traffic
                uint32_t a[2][4], bq[4][4];
                ldsm_x4(a[0], stA + arow[0] + csw[kse]);
                ldsm_x4(a[1], stA + arow[1] + csw[kse]);
                #pragma unroll
                for (int nb = 0; nb < 4; nb++)
                    ldsm_x4(bq[nb], stB + brow[nb] + csw[kse]);
                #pragma unroll
                for (int m2 = 0; m2 < 2; m2++){
                    #pragma unroll
                    for (int nb = 0; nb < 4; nb++){
                        asm volatile(
                            "mma.sync.aligned.m16n8k16.row.col.f32.bf16.bf16.f32 "
                            "{%0,%1,%2,%3}, {%4,%5,%6,%7}, {%8,%9}, {%0,%1,%2,%3};\n"
                            : "+f"(acc[m2][2*nb][0]), "+f"(acc[m2][2*nb][1]),
                              "+f"(acc[m2][2*nb][2]), "+f"(acc[m2][2*nb][3])
                            : "r"(a[m2][0]), "r"(a[m2][1]), "r"(a[m2][2]), "r"(a[m2][3]),
                              "r"(bq[nb][0]), "r"(bq[nb][2]));
                        asm volatile(
                            "mma.sync.aligned.m16n8k16.row.col.f32.bf16.bf16.f32 "
                            "{%0,%1,%2,%3}, {%4,%5,%6,%7}, {%8,%9}, {%0,%1,%2,%3};\n"
                            : "+f"(acc[m2][2*nb+1][0]), "+f"(acc[m2][2*nb+1][1]),
                              "+f"(acc[m2][2*nb+1][2]), "+f"(acc[m2][2*nb+1][3])
                            : "r"(a[m2][0]), "r"(a[m2][1]), "r"(a[m2][2]), "r"(a[m2][3]),
                              "r"(bq[nb][1]), "r"(bq[nb][3]));
                    }
                }
            }
            cur++; if (cur == 3) cur = 0;
        }

        // epilogue: accumulate into rs (pq/sv from L2; no staged-smem access)
        const float* svbase = g_scale_v + nc*128;
        float sv[16];
        #pragma unroll
        for (int nn = 0; nn < 8; nn++){
            sv[2*nn  ] = svbase[wn + nn*8 + t2];
            sv[2*nn+1] = svbase[wn + nn*8 + t2 + 1];
        }
        #pragma unroll
        for (int m2 = 0; m2 < 2; m2++){
            #pragma unroll
            for (int o = 0; o < 2; o++){
                int b = (wm + m2*16 + g + o*8) & 31;
                const float* prow = g_pq + (size_t)b*E_DIM + nc*128;
                float acc_s = 0.f;
                #pragma unroll
                for (int nn = 0; nn < 8; nn++){
                    int c = wn + nn*8 + t2;
                    acc_s += fast_tanh(acc[m2][nn][2*o  ] + prow[c  ]) * sv[2*nn  ]
                           + fast_tanh(acc[m2][nn][2*o+1] + prow[c+1]) * sv[2*nn+1];
                }
                rs[m2][o] += acc_s;
            }
        }
    }

    // single final reduction + write
    #pragma unroll
    for (int m2 = 0; m2 < 2; m2++)
        #pragma unroll
        for (int o = 0; o < 2; o++){
            rs[m2][o] += __shfl_xor_sync(0xffffffffu, rs[m2][o], 1);
            rs[m2][o] += __shfl_xor_sync(0xffffffffu, rs[m2][o], 2);
        }
    __syncthreads();
    if ((lane & 3) == 0){
        #pragma unroll
        for (int m2 = 0; m2 < 2; m2++)
            #pragma unroll
            for (int o = 0; o < 2; o++)
                sRed[(warp>>2)*128 + wm + m2*16 + o*8 + g] = rs[m2][o];
    }
    __syncthreads();
    if (tid < 128) g_scores[m0 + tid] = sRed[tid] + sRed[128 + tid];
}

// ---------------- kernel 5 (launch 5): softmax over s per b ----------------
__global__ void softmax_kernel(const unsigned char* __restrict__ mask,
                               float* __restrict__ out1, float* __restrict__ out2){
    __shared__ float red[32];
    __shared__ float bval;
    int b = blockIdx.x, s = threadIdx.x;
    int idx = s*B_DIM + b;
    float x = g_scores[idx];
    if (mask[idx]) x = -1e30f;

    float m = x;
    #pragma unroll
    for (int o=16;o;o>>=1) m = fmaxf(m, __shfl_xor_sync(0xffffffffu, m, o));
    if ((s&31)==0) red[s>>5] = m;
    __syncthreads();
    if (s < 32){
        float z = red[s];
        #pragma unroll
        for (int o=16;o;o>>=1) z = fmaxf(z, __shfl_xor_sync(0xffffffffu, z, o));
        if (s==0) bval = z;
    }
    __syncthreads();
    float e = __expf(x - bval);
    float t = e;
    #pragma unroll
    for (int o=16;o;o>>=1) t += __shfl_xor_sync(0xffffffffu, t, o);
    if ((s&31)==0) red[s>>5] = t;
    __syncthreads();
    if (s < 32){
        float z = red[s];
        #pragma unroll
        for (int o=16;o;o>>=1) z += __shfl_xor_sync(0xffffffffu, z, o);
        if (s==0) bval = z;
    }
    __syncthreads();
    float a = e / bval;
    g_scores[idx] = a;
    if (out1) out1[idx] = a;
    if (out2) out2[idx] = a;
}

// ---------------- kernel 6 (launch 6): context partials (fp32 value) ----------
__global__ void __launch_bounds__(256) context_part_kernel(const float* __restrict__ value){
    const int b = blockIdx.x, sc = blockIdx.y;
    const int d4 = threadIdx.x;
    const float4* v4 = reinterpret_cast<const float4*>(value);
    float4 acc = {0.f,0.f,0.f,0.f};
    const int s0 = sc * 256;
    #pragma unroll 1
    for (int s = s0; s < s0 + 256; s += 8){
        #pragma unroll
        for (int i = 0; i < 8; i++){
            float a = g_scores[(s+i)*B_DIM + b];
            float4 vv = v4[(size_t)((s+i)*B_DIM + b)*256 + d4];
            acc.x += a*vv.x; acc.y += a*vv.y; acc.z += a*vv.z; acc.w += a*vv.w;
        }
    }
    reinterpret_cast<float4*>(g_ctx_part)[(size_t)(sc*B_DIM + b)*256 + d4] = acc;
}

// ---------------- kernel 7 (launch 7): context reduce ----------------
__global__ void context_reduce_kernel(float* __restrict__ ctx){
    int b = blockIdx.x, d4 = threadIdx.x;
    const float4* p = reinterpret_cast<const float4*>(g_ctx_part);
    float4 a0 = p[(size_t)(0*B_DIM + b)*256 + d4];
    float4 a1 = p[(size_t)(1*B_DIM + b)*256 + d4];
    float4 a2 = p[(size_t)(2*B_DIM + b)*256 + d4];
    float4 a3 = p[(size_t)(3*B_DIM + b)*256 + d4];
    float4 o;
    o.x = (a0.x+a1.x)+(a2.x+a3.x);
    o.y = (a0.y+a1.y)+(a2.y+a3.y);
    o.z = (a0.z+a1.z)+(a2.z+a3.z);
    o.w = (a0.w+a1.w)+(a2.w+a3.w);
    reinterpret_cast<float4*>(ctx)[(size_t)b*256 + d4] = o;
}

// ---------------- launch ----------------
extern "C" void kernel_launch(void* const* d_in, const int* in_sizes, int n_in,
                              void* d_out, int out_size){
    const float* query = (const float*)d_in[0];
    const float* value = (const float*)d_in[1];
    const unsigned char* mask = (const unsigned char*)d_in[2];
    const float* Wq = (const float*)d_in[3];
    const float* bq = (const float*)d_in[4];
    const float* Wv = (const float*)d_in[5];
    const float* v  = (const float*)d_in[6];
    const float* g  = (const float*)d_in[7];
    float* out = (float*)d_out;
    (void)in_sizes; (void)n_in;

    cudaFuncSetAttribute(score_mma_kernel, cudaFuncAttributeMaxDynamicSharedMemorySize, SMEM_TOTAL);

    prep_kernel<<<17409, 256>>>(value, Wv, v, g);          // launch 1
    pq_part_kernel<<<dim3(128,8), 256>>>(query, Wq);       // launch 2
    pq_reduce_kernel<<<128, 256>>>(bq);                    // launch 3
    score_mma_kernel<<<256, 256, SMEM_TOTAL>>>();          // launch 4 (profiled)

    float* attn1 = (out_size >= 65536) ? out + 32768 : nullptr;
    float* attn2 = (out_size >= 98304) ? out + 65536 : nullptr;
    softmax_kernel<<<32, 1024>>>(mask, attn1, attn2);      // launch 5
    context_part_kernel<<<dim3(32,4), 256>>>(value);       // launch 6
    context_reduce_kernel<<<32, 256>>>(out);               // launch 7
}

// round 12
// speedup vs baseline: 1.1139x; 1.0579x over previous
#include <cuda_runtime.h>
#include <cuda_bf16.h>
#include <cstdint>

#define S_DIM 1024
#define B_DIM 32
#define D_DIM 1024
#define E_DIM 1024
#define M_TOTAL (S_DIM*B_DIM)

// ---------------- device scratch ----------------
__device__ __nv_bfloat16 g_wv_bf[E_DIM*D_DIM];
__device__ __nv_bfloat16 g_val_bf[(size_t)M_TOTAL*D_DIM];
__device__ float g_pq[B_DIM*E_DIM];
__device__ float g_pq_part[8*B_DIM*E_DIM];
__device__ float g_scale_v[E_DIM];
__device__ float g_scores[M_TOTAL];          // raw scores -> attn
__device__ float g_ctx_part[4*B_DIM*D_DIM];  // context s-split partials

__device__ __forceinline__ float fast_tanh(float x){
    float y; asm("tanh.approx.f32 %0, %1;" : "=f"(y) : "f"(x)); return y;
}
__device__ __forceinline__ uint32_t smem_u32(const void* p){
    return (uint32_t)__cvta_generic_to_shared(p);
}
__device__ __forceinline__ void cp_async16(uint32_t dst, const void* src){
    asm volatile("cp.async.cg.shared.global [%0], [%1], 16;\n" :: "r"(dst), "l"(src));
}
__device__ __forceinline__ void ldsm_x4(uint32_t* r, uint32_t addr){
    asm volatile("ldmatrix.sync.aligned.m8n8.x4.shared.b16 {%0,%1,%2,%3}, [%4];"
                 : "=r"(r[0]), "=r"(r[1]), "=r"(r[2]), "=r"(r[3]) : "r"(addr));
}

// ---------------- kernel 1 (launch 1): fused prep ----------------
__global__ void __launch_bounds__(256) prep_kernel(const float* __restrict__ value,
        const float* __restrict__ Wv, const float* __restrict__ v,
        const float* __restrict__ g){
    const int bid = blockIdx.x, tid = threadIdx.x;
    if (bid < 16384){
        size_t i = (size_t)bid*256 + tid;
        const float4* src = reinterpret_cast<const float4*>(value) + 2*i;
        float4 f0 = src[0], f1 = src[1];
        __nv_bfloat162 h0 = __floats2bfloat162_rn(f0.x, f0.y);
        __nv_bfloat162 h1 = __floats2bfloat162_rn(f0.z, f0.w);
        __nv_bfloat162 h2 = __floats2bfloat162_rn(f1.x, f1.y);
        __nv_bfloat162 h3 = __floats2bfloat162_rn(f1.z, f1.w);
        uint4 u;
        u.x = *(uint32_t*)&h0; u.y = *(uint32_t*)&h1;
        u.z = *(uint32_t*)&h2; u.w = *(uint32_t*)&h3;
        reinterpret_cast<uint4*>(g_val_bf)[i] = u;
    } else if (bid < 17408){
        int i = (bid - 16384)*256 + tid;
        float4 f = reinterpret_cast<const float4*>(Wv)[i];
        __nv_bfloat162* dst = reinterpret_cast<__nv_bfloat162*>(g_wv_bf) + 2*(size_t)i;
        dst[0] = __floats2bfloat162_rn(f.x, f.y);
        dst[1] = __floats2bfloat162_rn(f.z, f.w);
    } else {
        __shared__ float red[8];
        float4 xv = reinterpret_cast<const float4*>(v)[tid];
        float s = xv.x*xv.x + xv.y*xv.y + xv.z*xv.z + xv.w*xv.w;
        #pragma unroll
        for (int o=16;o;o>>=1) s += __shfl_xor_sync(0xffffffffu, s, o);
        if ((tid&31)==0) red[tid>>5] = s;
        __syncthreads();
        float tot = ((red[0]+red[1])+(red[2]+red[3])) + ((red[4]+red[5])+(red[6]+red[7]));
        float scale = g[0] / sqrtf(tot);
        float4 o4 = {scale*xv.x, scale*xv.y, scale*xv.z, scale*xv.w};
        reinterpret_cast<float4*>(g_scale_v)[tid] = o4;
    }
}

// ---------------- kernel 2 (launch 2): pq split-k ----------------
__global__ void __launch_bounds__(256) pq_part_kernel(const float* __restrict__ query,
                                                      const float* __restrict__ Wq){
    __shared__ float4 sQ4[32*33];
    __shared__ float4 sW4[8*33];
    const int tid = threadIdx.x;
    const int eb = blockIdx.x, kb = blockIdx.y;
    const float4* query4 = reinterpret_cast<const float4*>(query);
    const float4* Wq4 = reinterpret_cast<const float4*>(Wq);
    #pragma unroll
    for (int t = 0; t < 4; t++){
        int idx = tid + t*256;
        int b = idx >> 5, k4 = idx & 31;
        sQ4[b*33 + k4] = query4[b*256 + kb*32 + k4];
    }
    {
        int e = tid >> 5, k4 = tid & 31;
        sW4[e*33 + k4] = Wq4[(size_t)(eb*8+e)*256 + kb*32 + k4];
    }
    __syncthreads();
    const int b = tid & 31, e = tid >> 5;
    float a0 = 0.f, a1 = 0.f;
    #pragma unroll
    for (int k4 = 0; k4 < 32; k4 += 2){
        float4 w0 = sW4[e*33 + k4],   q0 = sQ4[b*33 + k4];
        float4 w1 = sW4[e*33 + k4+1], q1 = sQ4[b*33 + k4+1];
        a0 += w0.x*q0.x + w0.y*q0.y + w0.z*q0.z + w0.w*q0.w;
        a1 += w1.x*q1.x + w1.y*q1.y + w1.z*q1.z + w1.w*q1.w;
    }
    g_pq_part[((size_t)kb*32 + b)*1024 + eb*8 + e] = a0 + a1;
}

// ---------------- kernel 3 (launch 3): pq reduce ----------------
__global__ void pq_reduce_kernel(const float* __restrict__ bq){
    int idx = blockIdx.x*256 + threadIdx.x;
    int e = idx & 1023;
    float s = bq[e];
    #pragma unroll
    for (int kb = 0; kb < 8; kb++) s += g_pq_part[(size_t)kb*32768 + idx];
    g_pq[idx] = s;
}

// ---------------- kernel 4 (launch 4 -> PROFILED): score kernel ----------------
// grid 256, block 128 (4 warps of 64x64), 2 CTAs/SM, BM=128/BN=128.
// E in 8 chunks of 128, K in 64-wide chunks, 3-stage cp.async ring, SW128.
#define KSTAGES 3
#define STAGE_BYTES 32768
#define OFF_RED (KSTAGES*STAGE_BYTES)
#define SMEM_TOTAL (OFF_RED + 2*128*4)

__device__ __forceinline__ void score_load_stage(uint32_t sb, int m0, int cr, int cc,
                                                 int stage, int gk){
    const int i = gk & 15, nc = gk >> 4;
    const __nv_bfloat16* Abase = g_val_bf + (size_t)m0*D_DIM + i*64;
    const __nv_bfloat16* Bbase = g_wv_bf + (size_t)(nc*128)*D_DIM + i*64;
    uint32_t dA = sb + stage*STAGE_BYTES, dB = dA + 16384;
    #pragma unroll
    for (int t = 0; t < 8; t++){                    // 128 threads x 8 = 1024 chunks
        int r = cr + t*16;
        uint32_t off = (uint32_t)(r*128 + cc*16);
        off ^= (off>>3)&0x70;
        cp_async16(dA + off, Abase + (size_t)r*D_DIM + cc*8);
        cp_async16(dB + off, Bbase + (size_t)r*D_DIM + cc*8);
    }
    asm volatile("cp.async.commit_group;\n");
}

__global__ void __launch_bounds__(128,2) score_mma_kernel(){
    extern __shared__ char smem[];
    const uint32_t sb = smem_u32(smem);
    const int tid = threadIdx.x, lane = tid & 31, warp = tid >> 5;
    const int m0 = blockIdx.x * 128;
    const int wm = (warp & 1) * 64;      // M half
    const int wn = (warp >> 1) * 64;     // N half
    const int g  = lane >> 2, t2 = (lane & 3) * 2;
    float* sRed = (float*)(smem + OFF_RED);

    const uint32_t lrow = ((lane >> 3) & 1) * 8 + (lane & 7);
    const uint32_t hi = lane >> 4;
    const uint32_t xsw = lrow & 7;
    uint32_t arow[4], brow[4];
    #pragma unroll
    for (int m2 = 0; m2 < 4; m2++) arow[m2] = (wm + m2*16 + lrow)*128;
    #pragma unroll
    for (int nb = 0; nb < 4; nb++) brow[nb] = (wn + nb*16 + lrow)*128;
    uint32_t csw[4];
    #pragma unroll
    for (int ks = 0; ks < 4; ks++) csw[ks] = (((uint32_t)(ks*2) + hi) ^ xsw) << 4;

    const int cr = tid >> 3, cc = tid & 7;

    float rs[4][2];
    #pragma unroll
    for (int i=0;i<4;i++){ rs[i][0]=0.f; rs[i][1]=0.f; }

    score_load_stage(sb, m0, cr, cc, 0, 0);
    score_load_stage(sb, m0, cr, cc, 1, 1);

    int cur = 0;
    for (int nc = 0; nc < 8; nc++){
        float acc[4][8][4];
        #pragma unroll
        for (int i=0;i<4;i++)
            #pragma unroll
            for (int j=0;j<8;j++)
                #pragma unroll
                for (int k=0;k<4;k++) acc[i][j][k]=0.f;

        #pragma unroll 1
        for (int i = 0; i < 16; i++){
            const int gk = nc*16 + i;
            if (gk == 127) asm volatile("cp.async.wait_group 0;\n");
            else           asm volatile("cp.async.wait_group 1;\n");
            __syncthreads();
            if (gk + 2 < 128){
                int pf = cur + 2; if (pf >= 3) pf -= 3;
                score_load_stage(sb, m0, cr, cc, pf, gk + 2);
            }
            const uint32_t stA = sb + cur*STAGE_BYTES;
            const uint32_t stB = stA + 16384;
            #pragma unroll
            for (int ks = 0; ks < 4; ks++){
                uint32_t a[4][4], bq[4][4];
                #pragma unroll
                for (int m2 = 0; m2 < 4; m2++)
                    ldsm_x4(a[m2], stA + arow[m2] + csw[ks]);
                #pragma unroll
                for (int nb = 0; nb < 4; nb++)
                    ldsm_x4(bq[nb], stB + brow[nb] + csw[ks]);
                #pragma unroll
                for (int m2 = 0; m2 < 4; m2++){
                    #pragma unroll
                    for (int nb = 0; nb < 4; nb++){
                        asm volatile(
                            "mma.sync.aligned.m16n8k16.row.col.f32.bf16.bf16.f32 "
                            "{%0,%1,%2,%3}, {%4,%5,%6,%7}, {%8,%9}, {%0,%1,%2,%3};\n"
                            : "+f"(acc[m2][2*nb][0]), "+f"(acc[m2][2*nb][1]),
                              "+f"(acc[m2][2*nb][2]), "+f"(acc[m2][2*nb][3])
                            : "r"(a[m2][0]), "r"(a[m2][1]), "r"(a[m2][2]), "r"(a[m2][3]),
                              "r"(bq[nb][0]), "r"(bq[nb][2]));
                        asm volatile(
                            "mma.sync.aligned.m16n8k16.row.col.f32.bf16.bf16.f32 "
                            "{%0,%1,%2,%3}, {%4,%5,%6,%7}, {%8,%9}, {%0,%1,%2,%3};\n"
                            : "+f"(acc[m2][2*nb+1][0]), "+f"(acc[m2][2*nb+1][1]),
                              "+f"(acc[m2][2*nb+1][2]), "+f"(acc[m2][2*nb+1][3])
                            : "r"(a[m2][0]), "r"(a[m2][1]), "r"(a[m2][2]), "r"(a[m2][3]),
                              "r"(bq[nb][1]), "r"(bq[nb][3]));
                    }
                }
            }
            cur++; if (cur == 3) cur = 0;
        }

        // epilogue: accumulate into rs (pq/sv from L2; no staged-smem access)
        const float* svbase = g_scale_v + nc*128;
        float sv[16];
        #pragma unroll
        for (int nn = 0; nn < 8; nn++){
            sv[2*nn  ] = svbase[wn + nn*8 + t2];
            sv[2*nn+1] = svbase[wn + nn*8 + t2 + 1];
        }
        #pragma unroll
        for (int m2 = 0; m2 < 4; m2++){
            #pragma unroll
            for (int o = 0; o < 2; o++){
                int b = (wm + m2*16 + g + o*8) & 31;
                const float* prow = g_pq + (size_t)b*E_DIM + nc*128;
                float acc_s = 0.f;
                #pragma unroll
                for (int nn = 0; nn < 8; nn++){
                    int c = wn + nn*8 + t2;
                    acc_s += fast_tanh(acc[m2][nn][2*o  ] + prow[c  ]) * sv[2*nn  ]
                           + fast_tanh(acc[m2][nn][2*o+1] + prow[c+1]) * sv[2*nn+1];
                }
                rs[m2][o] += acc_s;
            }
        }
    }

    // final reduction: quad lanes, then the 2 N-warps per M-half
    #pragma unroll
    for (int m2 = 0; m2 < 4; m2++)
        #pragma unroll
        for (int o = 0; o < 2; o++){
            rs[m2][o] += __shfl_xor_sync(0xffffffffu, rs[m2][o], 1);
            rs[m2][o] += __shfl_xor_sync(0xffffffffu, rs[m2][o], 2);
        }
    __syncthreads();
    if ((lane & 3) == 0){
        #pragma unroll
        for (int m2 = 0; m2 < 4; m2++)
            #pragma unroll
            for (int o = 0; o < 2; o++)
                sRed[(warp>>1)*128 + wm + m2*16 + o*8 + g] = rs[m2][o];
    }
    __syncthreads();
    g_scores[m0 + tid] = sRed[tid] + sRed[128 + tid];
}

// ---------------- kernel 5 (launch 5): softmax over s per b ----------------
__global__ void softmax_kernel(const unsigned char* __restrict__ mask,
                               float* __restrict__ out1, float* __restrict__ out2){
    __shared__ float red[32];
    __shared__ float bval;
    int b = blockIdx.x, s = threadIdx.x;
    int idx = s*B_DIM + b;
    float x = g_scores[idx];
    if (mask[idx]) x = -1e30f;

    float m = x;
    #pragma unroll
    for (int o=16;o;o>>=1) m = fmaxf(m, __shfl_xor_sync(0xffffffffu, m, o));
    if ((s&31)==0) red[s>>5] = m;
    __syncthreads();
    if (s < 32){
        float z = red[s];
        #pragma unroll
        for (int o=16;o;o>>=1) z = fmaxf(z, __shfl_xor_sync(0xffffffffu, z, o));
        if (s==0) bval = z;
    }
    __syncthreads();
    float e = __expf(x - bval);
    float t = e;
    #pragma unroll
    for (int o=16;o;o>>=1) t += __shfl_xor_sync(0xffffffffu, t, o);
    if ((s&31)==0) red[s>>5] = t;
    __syncthreads();
    if (s < 32){
        float z = red[s];
        #pragma unroll
        for (int o=16;o;o>>=1) z += __shfl_xor_sync(0xffffffffu, z, o);
        if (s==0) bval = z;
    }
    __syncthreads();
    float a = e / bval;
    g_scores[idx] = a;
    if (out1) out1[idx] = a;
    if (out2) out2[idx] = a;
}

// ---------------- kernel 6 (launch 6): context partials (fp32 value) ----------
__global__ void __launch_bounds__(256) context_part_kernel(const float* __restrict__ value){
    const int b = blockIdx.x, sc = blockIdx.y;
    const int d4 = threadIdx.x;
    const float4* v4 = reinterpret_cast<const float4*>(value);
    float4 acc = {0.f,0.f,0.f,0.f};
    const int s0 = sc * 256;
    #pragma unroll 1
    for (int s = s0; s < s0 + 256; s += 8){
        #pragma unroll
        for (int i = 0; i < 8; i++){
            float a = g_scores[(s+i)*B_DIM + b];
            float4 vv = v4[(size_t)((s+i)*B_DIM + b)*256 + d4];
            acc.x += a*vv.x; acc.y += a*vv.y; acc.z += a*vv.z; acc.w += a*vv.w;
        }
    }
    reinterpret_cast<float4*>(g_ctx_part)[(size_t)(sc*B_DIM + b)*256 + d4] = acc;
}

// ---------------- kernel 7 (launch 7): context reduce ----------------
__global__ void context_reduce_kernel(float* __restrict__ ctx){
    int b = blockIdx.x, d4 = threadIdx.x;
    const float4* p = reinterpret_cast<const float4*>(g_ctx_part);
    float4 a0 = p[(size_t)(0*B_DIM + b)*256 + d4];
    float4 a1 = p[(size_t)(1*B_DIM + b)*256 + d4];
    float4 a2 = p[(size_t)(2*B_DIM + b)*256 + d4];
    float4 a3 = p[(size_t)(3*B_DIM + b)*256 + d4];
    float4 o;
    o.x = (a0.x+a1.x)+(a2.x+a3.x);
    o.y = (a0.y+a1.y)+(a2.y+a3.y);
    o.z = (a0.z+a1.z)+(a2.z+a3.z);
    o.w = (a0.w+a1.w)+(a2.w+a3.w);
    reinterpret_cast<float4*>(ctx)[(size_t)b*256 + d4] = o;
}

// ---------------- launch ----------------
extern "C" void kernel_launch(void* const* d_in, const int* in_sizes, int n_in,
                              void* d_out, int out_size){
    const float* query = (const float*)d_in[0];
    const float* value = (const float*)d_in[1];
    const unsigned char* mask = (const unsigned char*)d_in[2];
    const float* Wq = (const float*)d_in[3];
    const float* bq = (const float*)d_in[4];
    const float* Wv = (const float*)d_in[5];
    const float* v  = (const float*)d_in[6];
    const float* g  = (const float*)d_in[7];
    float* out = (float*)d_out;
    (void)in_sizes; (void)n_in;

    cudaFuncSetAttribute(score_mma_kernel, cudaFuncAttributeMaxDynamicSharedMemorySize, SMEM_TOTAL);

    prep_kernel<<<17409, 256>>>(value, Wv, v, g);          // launch 1
    pq_part_kernel<<<dim3(128,8), 256>>>(query, Wq);       // launch 2
    pq_reduce_kernel<<<128, 256>>>(bq);                    // launch 3
    score_mma_kernel<<<256, 128, SMEM_TOTAL>>>();          // launch 4 (profiled)

    float* attn1 = (out_size >= 65536) ? out + 32768 : nullptr;
    float* attn2 = (out_size >= 98304) ? out + 65536 : nullptr;
    softmax_kernel<<<32, 1024>>>(mask, attn1, attn2);      // launch 5
    context_part_kernel<<<dim3(32,4), 256>>>(value);       // launch 6
    context_reduce_kernel<<<32, 256>>>(out);               // launch 7
}